// round 2
// baseline (speedup 1.0000x reference)
#include <cuda_runtime.h>
#include <cstddef>

#define T_STEPS 32
#define NB      64
#define LEN0    2048
#define L1      1023
#define L2      511
#define C1      32
#define C2      64

// ---- output layout offsets (tuple of 8 stacked recs, concatenated flat) ----
static const size_t O_SPK0 = 0;
static const size_t O_SPK1 = (size_t)T_STEPS*NB*32736;
static const size_t O_SPK2 = O_SPK1 + (size_t)T_STEPS*NB*32704;
static const size_t O_SPK3 = O_SPK2 + (size_t)T_STEPS*NB*256;
static const size_t O_MEM0 = O_SPK3 + (size_t)T_STEPS*NB*2;
static const size_t O_MEM1 = O_MEM0 + (size_t)T_STEPS*NB*32736;
static const size_t O_MEM2 = O_MEM1 + (size_t)T_STEPS*NB*32704;
static const size_t O_MEM3 = O_MEM2 + (size_t)T_STEPS*NB*256;

// ---- persistent state / scratch ----
__device__ float    g_mem0[NB*C1*L1];
__device__ float    g_mem1[NB*C2*L2];
__device__ float    g_mem2[NB*256];
__device__ float    g_mem3[NB*2];
__device__ unsigned g_mask[NB*L1];
// LUT layout: [grp(8)][k*4+b4 (12)][v(256)][ocl(8)]
__device__ __align__(16) float g_lut[8*12*256*8];

// ================= compensated-arithmetic helpers =================
__device__ __forceinline__ void twoSum(float a, float b, float& s, float& e) {
    s = a + b;
    float bp = s - a;
    float ap = s - bp;
    e = (b - bp) + (a - ap);
}
__device__ __forceinline__ void kadd(float& s, float& c, float v) {
    float t, e;
    twoSum(s, v, t, e);
    c += e;
    s = t;
}
__device__ __forceinline__ void kfma(float& s, float& c, float a, float b) {
    float p = a * b;
    float e = fmaf(a, b, -p);   // exact product residual
    kadd(s, c, p);
    c += e;
}

// ================= init: zero membrane states =================
__global__ void k_init() {
    const int n0 = NB*C1*L1, n1 = NB*C2*L2, n2 = NB*256, n3 = NB*2;
    const int n = n0 + n1 + n2 + n3;
    for (int i = blockIdx.x*blockDim.x + threadIdx.x; i < n; i += gridDim.x*blockDim.x) {
        if (i < n0) g_mem0[i] = 0.f;
        else if (i < n0+n1) g_mem1[i-n0] = 0.f;
        else if (i < n0+n1+n2) g_mem2[i-n0-n1] = 0.f;
        else g_mem3[i-n0-n1-n2] = 0.f;
    }
}

// ================= LUT build: entries computed in double, rounded once ======
__global__ void k_lut(const float* __restrict__ w2) {
    int i = blockIdx.x*blockDim.x + threadIdx.x;
    if (i >= 8*12*256*8) return;
    int ocl = i & 7;
    int v   = (i >> 3) & 255;
    int t   = i >> 11;
    int kb  = t % 12;
    int g   = t / 12;
    int k   = kb >> 2;
    int b4  = kb & 3;
    int oc  = g*8 + ocl;
    double s = 0.0;
    #pragma unroll
    for (int bit = 0; bit < 8; bit++)
        if ((v >> bit) & 1)
            s += (double)w2[(oc*32 + b4*8 + bit)*3 + k];
    g_lut[i] = (float)s;
}

// ================= stage1: conv1 + maxpool + LIF0 =================
// grid (4, NB), block 256 ; thread = one l1 position
__global__ void __launch_bounds__(256) k_stage1(
        const float* __restrict__ x, const float* __restrict__ w1,
        const float* __restrict__ b1, const float* __restrict__ thr,
        float* __restrict__ out, int t)
{
    __shared__ float sw[C1*12];
    __shared__ float sb[C1];
    __shared__ float sthr;
    int b = blockIdx.y;
    for (int i = threadIdx.x; i < C1*12; i += 256) sw[i] = w1[i];
    if (threadIdx.x < C1) sb[threadIdx.x] = b1[threadIdx.x];
    if (threadIdx.x == 0) sthr = thr[0];
    __syncthreads();

    int l1 = blockIdx.x*256 + threadIdx.x;
    if (l1 >= L1) return;

    // x layout [B, T, C, L]
    const float* xb = x + (((size_t)b*T_STEPS + t)*4)*LEN0;
    float xr[4][5];
    #pragma unroll
    for (int c = 0; c < 4; c++)
        #pragma unroll
        for (int j = 0; j < 5; j++) {
            int gi = 2*l1 - 1 + j;
            xr[c][j] = (gi >= 0 && gi < LEN0) ? xb[c*LEN0 + gi] : 0.f;
        }

    const float th = sthr;
    unsigned mask = 0;
    for (int oc = 0; oc < C1; oc++) {
        float bb = sb[oc];
        // cheap float pass to find the pool-window argmax
        float y0 = bb, y1 = bb, y2 = bb;
        #pragma unroll
        for (int c = 0; c < 4; c++) {
            float w0 = sw[oc*12 + c*3 + 0];
            float w1v = sw[oc*12 + c*3 + 1];
            float w2v = sw[oc*12 + c*3 + 2];
            y0 = fmaf(w0, xr[c][0], fmaf(w1v, xr[c][1], fmaf(w2v, xr[c][2], y0)));
            y1 = fmaf(w0, xr[c][1], fmaf(w1v, xr[c][2], fmaf(w2v, xr[c][3], y1)));
            y2 = fmaf(w0, xr[c][2], fmaf(w1v, xr[c][3], fmaf(w2v, xr[c][4], y2)));
        }
        int dmax = 0;
        float ymax = y0;
        if (y1 > ymax) { ymax = y1; dmax = 1; }
        if (y2 > ymax) { ymax = y2; dmax = 2; }

        // exact recompute of the winning position (compensated)
        float s = bb, cc = 0.f;
        #pragma unroll
        for (int c = 0; c < 4; c++) {
            #pragma unroll
            for (int k = 0; k < 3; k++)
                kfma(s, cc, sw[oc*12 + c*3 + k], xr[c][dmax + k]);
        }
        float cur = s + cc;

        int   sidx = (b*C1 + oc)*L1 + l1;
        float mem  = g_mem0[sidx];
        float rst  = (mem - th > 0.f) ? 1.f : 0.f;
        float memn = fmaf(0.5f, mem, cur) - rst*th;
        g_mem0[sidx] = memn;
        float spk = (memn - th > 0.f) ? 1.f : 0.f;
        if (spk > 0.f) mask |= (1u << oc);
        size_t oi = ((size_t)t*NB + b)*32736 + (size_t)oc*L1 + l1;
        out[O_SPK0 + oi] = spk;
        out[O_MEM0 + oi] = memn;
    }
    g_mask[b*L1 + l1] = mask;
}

// ================= stage2: conv2 (LUT over spike bitmask) + maxpool + LIF1 ====
// grid (8 oc-groups, NB), block 256 ; dynamic smem: 96KB LUT(float4) + masks
__global__ void __launch_bounds__(256, 2) k_stage2(
        const float* __restrict__ b2, const float* __restrict__ thr,
        float* __restrict__ out, int t)
{
    extern __shared__ char smem_raw[];
    float4*   sT    = (float4*)smem_raw;                       // 6144 float4 = 96KB
    unsigned* smask = (unsigned*)(smem_raw + 6144*16);         // 1025 u32
    float*    sb2   = (float*)(smem_raw + 6144*16 + 1032*4);   // 8 + thr

    int b = blockIdx.y;
    int g = blockIdx.x;

    const float4* lut4 = (const float4*)g_lut + (size_t)g*12*256*2;
    for (int i = threadIdx.x; i < 12*256*2; i += 256) sT[i] = lut4[i];
    for (int i = threadIdx.x; i < L1+2; i += 256)
        smask[i] = (i >= 1 && i <= L1) ? g_mask[b*L1 + (i-1)] : 0u;
    if (threadIdx.x < 8) sb2[threadIdx.x] = b2[g*8 + threadIdx.x];
    if (threadIdx.x == 8) sb2[8] = thr[1];
    __syncthreads();

    const float th = sb2[8];

    for (int l2 = threadIdx.x; l2 < L2; l2 += 256) {
        float acc[3][8];
        #pragma unroll
        for (int d = 0; d < 3; d++)
            #pragma unroll
            for (int o = 0; o < 8; o++) acc[d][o] = 0.f;

        #pragma unroll
        for (int d = 0; d < 3; d++) {
            #pragma unroll
            for (int k = 0; k < 3; k++) {
                unsigned m = smask[2*l2 + d + k];
                // per-k partial over the 4 bytes, summed as a balanced tree
                float p[8];
                {
                    unsigned v0 = m & 255u;
                    unsigned v1 = (m >> 8) & 255u;
                    unsigned v2 = (m >> 16) & 255u;
                    unsigned v3 = (m >> 24) & 255u;
                    int k8 = (k*4) << 8;
                    int base0 = ((k8 | (int)v0) + 0*256) << 1;
                    int base1 = ((k8 | (int)v1) + 1*256) << 1;
                    int base2 = ((k8 | (int)v2) + 2*256) << 1;
                    int base3 = ((k8 | (int)v3) + 3*256) << 1;
                    float4 a0 = sT[base0],   a1 = sT[base0+1];
                    float4 c0 = sT[base1],   c1 = sT[base1+1];
                    float4 e0 = sT[base2],   e1 = sT[base2+1];
                    float4 f0 = sT[base3],   f1 = sT[base3+1];
                    p[0] = (a0.x + c0.x) + (e0.x + f0.x);
                    p[1] = (a0.y + c0.y) + (e0.y + f0.y);
                    p[2] = (a0.z + c0.z) + (e0.z + f0.z);
                    p[3] = (a0.w + c0.w) + (e0.w + f0.w);
                    p[4] = (a1.x + c1.x) + (e1.x + f1.x);
                    p[5] = (a1.y + c1.y) + (e1.y + f1.y);
                    p[6] = (a1.z + c1.z) + (e1.z + f1.z);
                    p[7] = (a1.w + c1.w) + (e1.w + f1.w);
                }
                #pragma unroll
                for (int o = 0; o < 8; o++) acc[d][o] += p[o];
            }
        }

        #pragma unroll
        for (int o = 0; o < 8; o++) {
            float c0 = acc[0][o] + sb2[o];
            float c1 = acc[1][o] + sb2[o];
            float c2 = acc[2][o] + sb2[o];
            float cur = fmaxf(c0, fmaxf(c1, c2));
            int oc = g*8 + o;
            int sidx = (b*C2 + oc)*L2 + l2;
            float mem  = g_mem1[sidx];
            float rst  = (mem - th > 0.f) ? 1.f : 0.f;
            float memn = fmaf(0.5f, mem, cur) - rst*th;
            g_mem1[sidx] = memn;
            float spk = (memn - th > 0.f) ? 1.f : 0.f;
            size_t oi = ((size_t)t*NB + b)*32704 + (size_t)oc*L2 + l2;
            out[O_SPK1 + oi] = spk;
            out[O_MEM1 + oi] = memn;
        }
    }
}

// ================= stage3: avgpool + fc1 + LIF2 + fc2 + LIF3 =================
// grid NB, block 256
__global__ void __launch_bounds__(256) k_stage3(
        const float* __restrict__ fc1w, const float* __restrict__ fc1b,
        const float* __restrict__ fc2w, const float* __restrict__ fc2b,
        const float* __restrict__ thr, float* __restrict__ out, int t)
{
    int b = blockIdx.x;
    int tid = threadIdx.x;
    __shared__ float feat[128];
    __shared__ float fc1o[256];
    __shared__ float spk2s[256];

    // ---- adaptive avg pool over spk1 (exact: integer sums / 256) ----
    {
        int oc = tid >> 2, sub = tid & 3;
        const float* sp = out + O_SPK1 + ((size_t)t*NB + b)*32704 + (size_t)oc*L2;
        float s0 = 0.f, s1 = 0.f;
        #pragma unroll 4
        for (int l2 = sub; l2 < L2; l2 += 4) {
            float v = sp[l2];
            if (l2 < 256) s0 += v;
            if (l2 >= 255) s1 += v;
        }
        s0 += __shfl_xor_sync(0xffffffffu, s0, 1);
        s0 += __shfl_xor_sync(0xffffffffu, s0, 2);
        s1 += __shfl_xor_sync(0xffffffffu, s1, 1);
        s1 += __shfl_xor_sync(0xffffffffu, s1, 2);
        if (sub == 0) {
            feat[oc*2 + 0] = s0 * (1.f/256.f);
            feat[oc*2 + 1] = s1 * (1.f/256.f);
        }
    }
    __syncthreads();

    // ---- fc1: warp-cooperative, compensated accumulation ----
    {
        int w = tid >> 5, lane = tid & 31;
        for (int oo = 0; oo < 32; oo++) {
            int o = w*32 + oo;
            float s = 0.f, c = 0.f;
            #pragma unroll
            for (int j = 0; j < 4; j++) {
                int f = lane + 32*j;
                kfma(s, c, fc1w[o*128 + f], feat[f]);
            }
            #pragma unroll
            for (int sh = 16; sh; sh >>= 1) {
                float s2 = __shfl_down_sync(0xffffffffu, s, sh);
                float c2 = __shfl_down_sync(0xffffffffu, c, sh);
                float tt, ee;
                twoSum(s, s2, tt, ee);
                c = (c + c2) + ee;
                s = tt;
            }
            if (lane == 0) fc1o[o] = s + c;
        }
    }
    __syncthreads();

    // ---- LIF2 ----
    {
        float th = thr[2];
        int o = tid;
        float cur = fc1o[o] + fc1b[o];
        float mem  = g_mem2[b*256 + o];
        float rst  = (mem - th > 0.f) ? 1.f : 0.f;
        float memn = fmaf(0.5f, mem, cur) - rst*th;
        g_mem2[b*256 + o] = memn;
        float spk = (memn - th > 0.f) ? 1.f : 0.f;
        spk2s[o] = spk;
        size_t oi = ((size_t)t*NB + b)*256 + o;
        out[O_SPK2 + oi] = spk;
        out[O_MEM2 + oi] = memn;
    }
    __syncthreads();

    // ---- fc2 + LIF3 (compensated; products are exact since spk in {0,1}) ----
    if (tid < 32) {
        float a0 = 0.f, e0 = 0.f, a1 = 0.f, e1 = 0.f;
        #pragma unroll
        for (int j = 0; j < 8; j++) {
            int o = tid + 32*j;
            float s = spk2s[o];
            kadd(a0, e0, fc2w[o] * s);        // exact product (s is 0/1)
            kadd(a1, e1, fc2w[256 + o] * s);
        }
        #pragma unroll
        for (int sh = 16; sh; sh >>= 1) {
            float s2 = __shfl_down_sync(0xffffffffu, a0, sh);
            float c2 = __shfl_down_sync(0xffffffffu, e0, sh);
            float tt, ee;
            twoSum(a0, s2, tt, ee);
            e0 = (e0 + c2) + ee; a0 = tt;
            s2 = __shfl_down_sync(0xffffffffu, a1, sh);
            c2 = __shfl_down_sync(0xffffffffu, e1, sh);
            twoSum(a1, s2, tt, ee);
            e1 = (e1 + c2) + ee; a1 = tt;
        }
        if (tid == 0) {
            float th = thr[3];
            float cc[2] = {(a0 + e0) + fc2b[0], (a1 + e1) + fc2b[1]};
            #pragma unroll
            for (int r = 0; r < 2; r++) {
                float mem  = g_mem3[b*2 + r];
                float rst  = (mem - th > 0.f) ? 1.f : 0.f;
                float memn = fmaf(0.5f, mem, cc[r]) - rst*th;
                g_mem3[b*2 + r] = memn;
                float spk = (memn - th > 0.f) ? 1.f : 0.f;
                size_t oi = ((size_t)t*NB + b)*2 + r;
                out[O_SPK3 + oi] = spk;
                out[O_MEM3 + oi] = memn;
            }
        }
    }
}

extern "C" void kernel_launch(void* const* d_in, const int* in_sizes, int n_in,
                              void* d_out, int out_size)
{
    const float* x   = (const float*)d_in[0];
    const float* c1w = (const float*)d_in[1];
    const float* c1b = (const float*)d_in[2];
    const float* c2w = (const float*)d_in[3];
    const float* c2b = (const float*)d_in[4];
    const float* f1w = (const float*)d_in[5];
    const float* f1b = (const float*)d_in[6];
    const float* f2w = (const float*)d_in[7];
    const float* f2b = (const float*)d_in[8];
    const float* thr = (const float*)d_in[9];
    float* out = (float*)d_out;

    const int smem2 = 6144*16 + 1032*4 + 16*4;
    cudaFuncSetAttribute(k_stage2, cudaFuncAttributeMaxDynamicSharedMemorySize, smem2);

    k_init<<<256, 256>>>();
    k_lut<<<(8*12*256*8 + 255)/256, 256>>>(c2w);
    for (int t = 0; t < T_STEPS; t++) {
        k_stage1<<<dim3(4, NB), 256>>>(x, c1w, c1b, thr, out, t);
        k_stage2<<<dim3(8, NB), 256, smem2>>>(c2b, thr, out, t);
        k_stage3<<<NB, 256>>>(f1w, f1b, f2w, f2b, thr, out, t);
    }
}

// round 3
// speedup vs baseline: 1.4703x; 1.4703x over previous
#include <cuda_runtime.h>
#include <cstddef>

#define T_STEPS 32
#define NB      64
#define LEN0    2048
#define L1      1023
#define L2      511
#define C1      32
#define C2      64

// ---- output layout offsets ----
static const size_t O_SPK0 = 0;
static const size_t O_SPK1 = (size_t)T_STEPS*NB*32736;
static const size_t O_SPK2 = O_SPK1 + (size_t)T_STEPS*NB*32704;
static const size_t O_SPK3 = O_SPK2 + (size_t)T_STEPS*NB*256;
static const size_t O_MEM0 = O_SPK3 + (size_t)T_STEPS*NB*2;
static const size_t O_MEM1 = O_MEM0 + (size_t)T_STEPS*NB*32736;
static const size_t O_MEM2 = O_MEM1 + (size_t)T_STEPS*NB*32704;
static const size_t O_MEM3 = O_MEM2 + (size_t)T_STEPS*NB*256;

// ---- persistent state / scratch ----
__device__ float    g_mem0[NB*C1*L1];
__device__ float    g_mem1[NB*C2*L2];
__device__ float    g_mem2[NB*256];
__device__ float    g_mem3[NB*2];
__device__ unsigned g_mask[NB*L1];
__device__ float    g_feat[2*NB*128];     // double-buffered avgpool features
// LUT: [grp(16)][kb(12)][v(256)] float4 (4 oc per group)
__device__ __align__(16) float g_lut[16*12*256*4];

// smem layout constants for k_fused stage2 path
#define SM_T    0
#define SM_MASK 49152
#define SM_SC   (49152 + 4128)
#define SM_AUX  (49152 + 4128 + 16368)
#define SMEM2   (SM_AUX + 64)

// ================= compensated-arithmetic helpers =================
__device__ __forceinline__ void twoSum(float a, float b, float& s, float& e) {
    s = a + b;
    float bp = s - a;
    float ap = s - bp;
    e = (b - bp) + (a - ap);
}
__device__ __forceinline__ void kadd(float& s, float& c, float v) {
    float t, e;
    twoSum(s, v, t, e);
    c += e;
    s = t;
}
__device__ __forceinline__ void kfma(float& s, float& c, float a, float b) {
    float p = a * b;
    float e = fmaf(a, b, -p);
    kadd(s, c, p);
    c += e;
}

// ================= init: zero membrane states =================
__global__ void k_init() {
    const int n0 = NB*C1*L1, n1 = NB*C2*L2, n2 = NB*256, n3 = NB*2;
    const int n = n0 + n1 + n2 + n3;
    for (int i = blockIdx.x*blockDim.x + threadIdx.x; i < n; i += gridDim.x*blockDim.x) {
        if (i < n0) g_mem0[i] = 0.f;
        else if (i < n0+n1) g_mem1[i-n0] = 0.f;
        else if (i < n0+n1+n2) g_mem2[i-n0-n1] = 0.f;
        else g_mem3[i-n0-n1-n2] = 0.f;
    }
}

// ================= LUT build (double, rounded once) =================
__global__ void k_lut(const float* __restrict__ w2) {
    int i = blockIdx.x*blockDim.x + threadIdx.x;
    if (i >= 16*12*256*4) return;
    int ocl = i & 3;
    int v   = (i >> 2) & 255;
    int tt  = i >> 10;
    int kb  = tt % 12;
    int g   = tt / 12;
    int k   = kb >> 2;
    int b4  = kb & 3;
    int oc  = g*4 + ocl;
    double s = 0.0;
    #pragma unroll
    for (int bit = 0; bit < 8; bit++)
        if ((v >> bit) & 1)
            s += (double)w2[(oc*32 + b4*8 + bit)*3 + k];
    g_lut[i] = (float)s;
}

// ================= stage1: conv1 + maxpool + LIF0 (numerics == round 2) =====
__global__ void __launch_bounds__(256) k_stage1(
        const float* __restrict__ x, const float* __restrict__ w1,
        const float* __restrict__ b1, const float* __restrict__ thr,
        float* __restrict__ out, int t)
{
    __shared__ float sw[C1*12];
    __shared__ float sb[C1];
    __shared__ float sthr;
    int b = blockIdx.y;
    for (int i = threadIdx.x; i < C1*12; i += 256) sw[i] = w1[i];
    if (threadIdx.x < C1) sb[threadIdx.x] = b1[threadIdx.x];
    if (threadIdx.x == 0) sthr = thr[0];
    __syncthreads();

    int l1 = blockIdx.x*256 + threadIdx.x;
    if (l1 >= L1) return;

    const float* xb = x + (((size_t)b*T_STEPS + t)*4)*LEN0;
    float xr[4][5];
    #pragma unroll
    for (int c = 0; c < 4; c++)
        #pragma unroll
        for (int j = 0; j < 5; j++) {
            int gi = 2*l1 - 1 + j;
            xr[c][j] = (gi >= 0 && gi < LEN0) ? xb[c*LEN0 + gi] : 0.f;
        }

    const float th = sthr;
    unsigned mask = 0;
    #pragma unroll 2
    for (int oc = 0; oc < C1; oc++) {
        float bb = sb[oc];
        float y0 = bb, y1 = bb, y2 = bb;
        #pragma unroll
        for (int c = 0; c < 4; c++) {
            float w0 = sw[oc*12 + c*3 + 0];
            float w1v = sw[oc*12 + c*3 + 1];
            float w2v = sw[oc*12 + c*3 + 2];
            y0 = fmaf(w0, xr[c][0], fmaf(w1v, xr[c][1], fmaf(w2v, xr[c][2], y0)));
            y1 = fmaf(w0, xr[c][1], fmaf(w1v, xr[c][2], fmaf(w2v, xr[c][3], y1)));
            y2 = fmaf(w0, xr[c][2], fmaf(w1v, xr[c][3], fmaf(w2v, xr[c][4], y2)));
        }
        int dmax = 0;
        float ymax = y0;
        if (y1 > ymax) { ymax = y1; dmax = 1; }
        if (y2 > ymax) { ymax = y2; dmax = 2; }

        float s = bb, cc = 0.f;
        #pragma unroll
        for (int c = 0; c < 4; c++) {
            #pragma unroll
            for (int k = 0; k < 3; k++)
                kfma(s, cc, sw[oc*12 + c*3 + k], xr[c][dmax + k]);
        }
        float cur = s + cc;

        int   sidx = (b*C1 + oc)*L1 + l1;
        float mem  = g_mem0[sidx];
        float rst  = (mem - th > 0.f) ? 1.f : 0.f;
        float memn = fmaf(0.5f, mem, cur) - rst*th;
        g_mem0[sidx] = memn;
        float spk = (memn - th > 0.f) ? 1.f : 0.f;
        if (spk > 0.f) mask |= (1u << oc);
        size_t oi = ((size_t)t*NB + b)*32736 + (size_t)oc*L1 + l1;
        out[O_SPK0 + oi] = spk;
        out[O_MEM0 + oi] = memn;
    }
    g_mask[b*L1 + l1] = mask;
}

// ================= fc path (fc1 + LIF2 + fc2 + LIF3) for step ts ============
__device__ __forceinline__ void fc_block(
        char* sm, int b, int ts,
        const float* __restrict__ fc1w, const float* __restrict__ fc1b,
        const float* __restrict__ fc2w, const float* __restrict__ fc2b,
        const float* __restrict__ thr, float* __restrict__ out)
{
    float* sfeat = (float*)sm;          // 128
    float* sfc1o = sfeat + 128;         // 256
    float* sspk2 = sfc1o + 256;         // 256
    int tid = threadIdx.x;

    if (tid < 128) sfeat[tid] = g_feat[(size_t)(ts&1)*NB*128 + b*128 + tid];
    __syncthreads();

    // fc1: warp-cooperative compensated
    {
        int w = tid >> 5, lane = tid & 31;
        for (int oo = 0; oo < 32; oo++) {
            int o = w*32 + oo;
            float s = 0.f, c = 0.f;
            #pragma unroll
            for (int j = 0; j < 4; j++) {
                int f = lane + 32*j;
                kfma(s, c, fc1w[o*128 + f], sfeat[f]);
            }
            #pragma unroll
            for (int sh = 16; sh; sh >>= 1) {
                float s2 = __shfl_down_sync(0xffffffffu, s, sh);
                float c2 = __shfl_down_sync(0xffffffffu, c, sh);
                float ttv, ee;
                twoSum(s, s2, ttv, ee);
                c = (c + c2) + ee;
                s = ttv;
            }
            if (lane == 0) sfc1o[o] = s + c;
        }
    }
    __syncthreads();

    // LIF2
    {
        float th = thr[2];
        int o = tid;
        float cur = sfc1o[o] + fc1b[o];
        float mem  = g_mem2[b*256 + o];
        float rst  = (mem - th > 0.f) ? 1.f : 0.f;
        float memn = fmaf(0.5f, mem, cur) - rst*th;
        g_mem2[b*256 + o] = memn;
        float spk = (memn - th > 0.f) ? 1.f : 0.f;
        sspk2[o] = spk;
        size_t oi = ((size_t)ts*NB + b)*256 + o;
        out[O_SPK2 + oi] = spk;
        out[O_MEM2 + oi] = memn;
    }
    __syncthreads();

    // fc2 + LIF3
    if (tid < 32) {
        float a0 = 0.f, e0 = 0.f, a1 = 0.f, e1 = 0.f;
        #pragma unroll
        for (int j = 0; j < 8; j++) {
            int o = tid + 32*j;
            float s = sspk2[o];
            kadd(a0, e0, fc2w[o] * s);
            kadd(a1, e1, fc2w[256 + o] * s);
        }
        #pragma unroll
        for (int sh = 16; sh; sh >>= 1) {
            float s2 = __shfl_down_sync(0xffffffffu, a0, sh);
            float c2 = __shfl_down_sync(0xffffffffu, e0, sh);
            float ttv, ee;
            twoSum(a0, s2, ttv, ee);
            e0 = (e0 + c2) + ee; a0 = ttv;
            s2 = __shfl_down_sync(0xffffffffu, a1, sh);
            c2 = __shfl_down_sync(0xffffffffu, e1, sh);
            twoSum(a1, s2, ttv, ee);
            e1 = (e1 + c2) + ee; a1 = ttv;
        }
        if (tid == 0) {
            float th = thr[3];
            float cc[2] = {(a0 + e0) + fc2b[0], (a1 + e1) + fc2b[1]};
            #pragma unroll
            for (int r = 0; r < 2; r++) {
                float mem  = g_mem3[b*2 + r];
                float rst  = (mem - th > 0.f) ? 1.f : 0.f;
                float memn = fmaf(0.5f, mem, cc[r]) - rst*th;
                g_mem3[b*2 + r] = memn;
                float spk = (memn - th > 0.f) ? 1.f : 0.f;
                size_t oi = ((size_t)ts*NB + b)*2 + r;
                out[O_SPK3 + oi] = spk;
                out[O_MEM3 + oi] = memn;
            }
        }
    }
}

// ================= fused: stage2(t) [+ avgpool] and stage3(t-1) =============
// blocks [0,1024): stage2 (16 oc-groups x 64 batch); blocks [1024,1088): fc(t-1)
__global__ void __launch_bounds__(256, 3) k_fused(
        const float* __restrict__ b2,
        const float* __restrict__ fc1w, const float* __restrict__ fc1b,
        const float* __restrict__ fc2w, const float* __restrict__ fc2b,
        const float* __restrict__ thr, float* __restrict__ out, int t)
{
    extern __shared__ char sm[];
    if (blockIdx.x >= 1024) {
        fc_block(sm, blockIdx.x - 1024, t - 1, fc1w, fc1b, fc2w, fc2b, thr, out);
        return;
    }

    float4*   sT    = (float4*)(sm + SM_T);      // 12*256 float4 = 48KB
    unsigned* smask = (unsigned*)(sm + SM_MASK); // 1032 u32
    float4*   sc    = (float4*)(sm + SM_SC);     // 1023 float4
    float*    saux  = (float*)(sm + SM_AUX);     // [0:8) counts, [8:12) bias, [12] thr

    int g = blockIdx.x & 15;
    int b = blockIdx.x >> 4;
    int tid = threadIdx.x;

    const float4* lutg = (const float4*)g_lut + (size_t)g*12*256;
    for (int i = tid; i < 12*256; i += 256) sT[i] = lutg[i];
    for (int i = tid; i < 1032; i += 256)
        smask[i] = (i >= 1 && i <= L1) ? g_mask[b*L1 + (i-1)] : 0u;
    if (tid < 8) saux[tid] = 0.f;
    if (tid >= 8 && tid < 12) saux[tid] = b2[g*4 + (tid-8)];
    if (tid == 12) saux[12] = thr[1];
    __syncthreads();

    // ---- pass A: conv outputs c[q], q in [0,1023), 4 per thread ----
    {
        int q0 = tid*4;
        unsigned mm[6];
        #pragma unroll
        for (int j = 0; j < 6; j++) mm[j] = smask[q0 + j];
        #pragma unroll
        for (int i = 0; i < 4; i++) {
            int q = q0 + i;
            if (q < L1) {
                float4 acc = make_float4(0.f, 0.f, 0.f, 0.f);
                #pragma unroll
                for (int k = 0; k < 3; k++) {
                    unsigned m = mm[i + k];
                    unsigned v0 = m & 255u, v1 = (m >> 8) & 255u;
                    unsigned v2 = (m >> 16) & 255u, v3 = m >> 24;
                    const float4* tk = sT + k*4*256;
                    float4 l0 = make_float4(0.f,0.f,0.f,0.f);
                    float4 l1 = l0, l2v = l0, l3 = l0;
                    if (v0) l0  = tk[v0];
                    if (v1) l1  = tk[256 + v1];
                    if (v2) l2v = tk[512 + v2];
                    if (v3) l3  = tk[768 + v3];
                    acc.x += (l0.x + l1.x) + (l2v.x + l3.x);
                    acc.y += (l0.y + l1.y) + (l2v.y + l3.y);
                    acc.z += (l0.z + l1.z) + (l2v.z + l3.z);
                    acc.w += (l0.w + l1.w) + (l2v.w + l3.w);
                }
                sc[q] = acc;
            }
        }
    }
    __syncthreads();

    // ---- pass B: maxpool + LIF1 + writes + spike counts ----
    const float th = saux[12];
    const float bs0 = saux[8], bs1 = saux[9], bs2 = saux[10], bs3 = saux[11];
    float cnt0[4] = {0.f,0.f,0.f,0.f}, cnt1[4] = {0.f,0.f,0.f,0.f};

    for (int l = tid; l < L2; l += 256) {
        float4 c0 = sc[2*l], c1 = sc[2*l + 1], c2 = sc[2*l + 2];
        float cur[4];
        cur[0] = fmaxf(c0.x + bs0, fmaxf(c1.x + bs0, c2.x + bs0));
        cur[1] = fmaxf(c0.y + bs1, fmaxf(c1.y + bs1, c2.y + bs1));
        cur[2] = fmaxf(c0.z + bs2, fmaxf(c1.z + bs2, c2.z + bs2));
        cur[3] = fmaxf(c0.w + bs3, fmaxf(c1.w + bs3, c2.w + bs3));
        #pragma unroll
        for (int o = 0; o < 4; o++) {
            int oc = g*4 + o;
            int sidx = (b*C2 + oc)*L2 + l;
            float mem  = g_mem1[sidx];
            float rst  = (mem - th > 0.f) ? 1.f : 0.f;
            float memn = fmaf(0.5f, mem, cur[o]) - rst*th;
            g_mem1[sidx] = memn;
            float spk = (memn - th > 0.f) ? 1.f : 0.f;
            size_t oi = ((size_t)t*NB + b)*32704 + (size_t)oc*L2 + l;
            out[O_SPK1 + oi] = spk;
            out[O_MEM1 + oi] = memn;
            if (l < 256)  cnt0[o] += spk;
            if (l >= 255) cnt1[o] += spk;
        }
    }

    // reduce counts (exact integer sums)
    {
        int lane = tid & 31;
        #pragma unroll
        for (int o = 0; o < 4; o++) {
            float a = cnt0[o], c = cnt1[o];
            #pragma unroll
            for (int sh = 16; sh; sh >>= 1) {
                a += __shfl_down_sync(0xffffffffu, a, sh);
                c += __shfl_down_sync(0xffffffffu, c, sh);
            }
            if (lane == 0) {
                atomicAdd(&saux[o*2 + 0], a);
                atomicAdd(&saux[o*2 + 1], c);
            }
        }
    }
    __syncthreads();
    if (tid < 8)
        g_feat[(size_t)(t&1)*NB*128 + b*128 + g*8 + tid] = saux[tid] * 0.00390625f;
}

// ================= tail: fc for t = 31 =================
__global__ void __launch_bounds__(256) k_tail(
        const float* __restrict__ fc1w, const float* __restrict__ fc1b,
        const float* __restrict__ fc2w, const float* __restrict__ fc2b,
        const float* __restrict__ thr, float* __restrict__ out)
{
    __shared__ char sm[(128 + 256 + 256) * 4];
    fc_block(sm, blockIdx.x, T_STEPS - 1, fc1w, fc1b, fc2w, fc2b, thr, out);
}

extern "C" void kernel_launch(void* const* d_in, const int* in_sizes, int n_in,
                              void* d_out, int out_size)
{
    const float* x   = (const float*)d_in[0];
    const float* c1w = (const float*)d_in[1];
    const float* c1b = (const float*)d_in[2];
    const float* c2w = (const float*)d_in[3];
    const float* c2b = (const float*)d_in[4];
    const float* f1w = (const float*)d_in[5];
    const float* f1b = (const float*)d_in[6];
    const float* f2w = (const float*)d_in[7];
    const float* f2b = (const float*)d_in[8];
    const float* thr = (const float*)d_in[9];
    float* out = (float*)d_out;

    cudaFuncSetAttribute(k_fused, cudaFuncAttributeMaxDynamicSharedMemorySize, SMEM2);

    k_init<<<256, 256>>>();
    k_lut<<<(16*12*256*4 + 255)/256, 256>>>(c2w);
    for (int t = 0; t < T_STEPS; t++) {
        k_stage1<<<dim3(4, NB), 256>>>(x, c1w, c1b, thr, out, t);
        int nblk = (t >= 1) ? 1088 : 1024;
        k_fused<<<nblk, 256, SMEM2>>>(c2b, f1w, f1b, f2w, f2b, thr, out, t);
    }
    k_tail<<<NB, 256>>>(f1w, f1b, f2w, f2b, thr, out);
}

// round 4
// speedup vs baseline: 1.6341x; 1.1114x over previous
#include <cuda_runtime.h>
#include <cstddef>

#define T_STEPS 32
#define NB      64
#define LEN0    2048
#define L1      1023
#define L2      511
#define C1      32
#define C2      64

// ---- output layout offsets ----
static const size_t O_SPK0 = 0;
static const size_t O_SPK1 = (size_t)T_STEPS*NB*32736;
static const size_t O_SPK2 = O_SPK1 + (size_t)T_STEPS*NB*32704;
static const size_t O_SPK3 = O_SPK2 + (size_t)T_STEPS*NB*256;
static const size_t O_MEM0 = O_SPK3 + (size_t)T_STEPS*NB*2;
static const size_t O_MEM1 = O_MEM0 + (size_t)T_STEPS*NB*32736;
static const size_t O_MEM2 = O_MEM1 + (size_t)T_STEPS*NB*32704;
static const size_t O_MEM3 = O_MEM2 + (size_t)T_STEPS*NB*256;

// ---- persistent state / scratch ----
__device__ float    g_mem0[NB*C1*L1];
__device__ float    g_mem1[NB*C2*L2];
__device__ float    g_mem2[NB*256];
__device__ float    g_mem3[NB*2];
__device__ unsigned g_mask[2][NB*L1];     // double-buffered spike bitmasks
__device__ float    g_feat[2*NB*128];     // double-buffered avgpool features
// LUT: [grp(16)][kb(12)][v(256)] float4 (4 oc per group)
__device__ __align__(16) float g_lut[16*12*256*4];

// smem layout for fused kernel (stage2 role)
#define SM_T    0
#define SM_MASK 49152
#define SM_SC   (49152 + 4128)
#define SM_AUX  (SM_SC + 16368)
#define SMEM2   (SM_AUX + 64)

// ================= compensated-arithmetic helpers =================
__device__ __forceinline__ void twoSum(float a, float b, float& s, float& e) {
    s = a + b;
    float bp = s - a;
    float ap = s - bp;
    e = (b - bp) + (a - ap);
}
__device__ __forceinline__ void kadd(float& s, float& c, float v) {
    float t, e;
    twoSum(s, v, t, e);
    c += e;
    s = t;
}
__device__ __forceinline__ void kfma(float& s, float& c, float a, float b) {
    float p = a * b;
    float e = fmaf(a, b, -p);
    kadd(s, c, p);
    c += e;
}

// ================= init: zero membrane states =================
__global__ void k_init() {
    const int n0 = NB*C1*L1, n1 = NB*C2*L2, n2 = NB*256, n3 = NB*2;
    const int n = n0 + n1 + n2 + n3;
    for (int i = blockIdx.x*blockDim.x + threadIdx.x; i < n; i += gridDim.x*blockDim.x) {
        if (i < n0) g_mem0[i] = 0.f;
        else if (i < n0+n1) g_mem1[i-n0] = 0.f;
        else if (i < n0+n1+n2) g_mem2[i-n0-n1] = 0.f;
        else g_mem3[i-n0-n1-n2] = 0.f;
    }
}

// ================= LUT build (double, rounded once) =================
__global__ void k_lut(const float* __restrict__ w2) {
    int i = blockIdx.x*blockDim.x + threadIdx.x;
    if (i >= 16*12*256*4) return;
    int ocl = i & 3;
    int v   = (i >> 2) & 255;
    int tt  = i >> 10;
    int kb  = tt % 12;
    int g   = tt / 12;
    int k   = kb >> 2;
    int b4  = kb & 3;
    int oc  = g*4 + ocl;
    double s = 0.0;
    #pragma unroll
    for (int bit = 0; bit < 8; bit++)
        if ((v >> bit) & 1)
            s += (double)w2[(oc*32 + b4*8 + bit)*3 + k];
    g_lut[i] = (float)s;
}

// ================= stage1 body: conv1 + maxpool + LIF0 =================
__device__ __forceinline__ void stage1_body(
        float* sw, float* sb, float* sthr,
        int b, int tile, int ts,
        const float* __restrict__ x, const float* __restrict__ w1,
        const float* __restrict__ b1, const float* __restrict__ thr,
        float* __restrict__ out)
{
    for (int i = threadIdx.x; i < C1*12; i += 256) sw[i] = w1[i];
    if (threadIdx.x < C1) sb[threadIdx.x] = b1[threadIdx.x];
    if (threadIdx.x == 0) sthr[0] = thr[0];
    __syncthreads();

    int l1 = tile*256 + threadIdx.x;
    if (l1 >= L1) return;

    const float* xb = x + (((size_t)b*T_STEPS + ts)*4)*LEN0;
    float xr[4][5];
    #pragma unroll
    for (int c = 0; c < 4; c++)
        #pragma unroll
        for (int j = 0; j < 5; j++) {
            int gi = 2*l1 - 1 + j;
            xr[c][j] = (gi >= 0 && gi < LEN0) ? xb[c*LEN0 + gi] : 0.f;
        }

    const float th = sthr[0];
    unsigned mask = 0;
    #pragma unroll 2
    for (int oc = 0; oc < C1; oc++) {
        float bb = sb[oc];
        float y0 = bb, y1 = bb, y2 = bb;
        #pragma unroll
        for (int c = 0; c < 4; c++) {
            float w0 = sw[oc*12 + c*3 + 0];
            float w1v = sw[oc*12 + c*3 + 1];
            float w2v = sw[oc*12 + c*3 + 2];
            y0 = fmaf(w0, xr[c][0], fmaf(w1v, xr[c][1], fmaf(w2v, xr[c][2], y0)));
            y1 = fmaf(w0, xr[c][1], fmaf(w1v, xr[c][2], fmaf(w2v, xr[c][3], y1)));
            y2 = fmaf(w0, xr[c][2], fmaf(w1v, xr[c][3], fmaf(w2v, xr[c][4], y2)));
        }
        int dmax = 0;
        float ymax = y0;
        if (y1 > ymax) { ymax = y1; dmax = 1; }
        if (y2 > ymax) { ymax = y2; dmax = 2; }

        float s = bb, cc = 0.f;
        #pragma unroll
        for (int c = 0; c < 4; c++) {
            #pragma unroll
            for (int k = 0; k < 3; k++)
                kfma(s, cc, sw[oc*12 + c*3 + k], xr[c][dmax + k]);
        }
        float cur = s + cc;

        int   sidx = (b*C1 + oc)*L1 + l1;
        float mem  = g_mem0[sidx];
        float rst  = (mem - th > 0.f) ? 1.f : 0.f;
        float memn = fmaf(0.5f, mem, cur) - rst*th;
        g_mem0[sidx] = memn;
        float spk = (memn - th > 0.f) ? 1.f : 0.f;
        if (spk > 0.f) mask |= (1u << oc);
        size_t oi = ((size_t)ts*NB + b)*32736 + (size_t)oc*L1 + l1;
        out[O_SPK0 + oi] = spk;
        out[O_MEM0 + oi] = memn;
    }
    g_mask[ts & 1][b*L1 + l1] = mask;
}

// ================= fc body (fc1 + LIF2 + fc2 + LIF3) for step ts ============
__device__ __forceinline__ void fc_block(
        char* sm, int b, int ts,
        const float* __restrict__ fc1w, const float* __restrict__ fc1b,
        const float* __restrict__ fc2w, const float* __restrict__ fc2b,
        const float* __restrict__ thr, float* __restrict__ out)
{
    float* sfeat = (float*)sm;          // 128
    float* sfc1o = sfeat + 128;         // 256
    float* sspk2 = sfc1o + 256;         // 256
    int tid = threadIdx.x;

    if (tid < 128) sfeat[tid] = g_feat[(size_t)(ts&1)*NB*128 + b*128 + tid];
    __syncthreads();

    {
        int w = tid >> 5, lane = tid & 31;
        for (int oo = 0; oo < 32; oo++) {
            int o = w*32 + oo;
            float s = 0.f, c = 0.f;
            #pragma unroll
            for (int j = 0; j < 4; j++) {
                int f = lane + 32*j;
                kfma(s, c, fc1w[o*128 + f], sfeat[f]);
            }
            #pragma unroll
            for (int sh = 16; sh; sh >>= 1) {
                float s2 = __shfl_down_sync(0xffffffffu, s, sh);
                float c2 = __shfl_down_sync(0xffffffffu, c, sh);
                float ttv, ee;
                twoSum(s, s2, ttv, ee);
                c = (c + c2) + ee;
                s = ttv;
            }
            if (lane == 0) sfc1o[o] = s + c;
        }
    }
    __syncthreads();

    {
        float th = thr[2];
        int o = tid;
        float cur = sfc1o[o] + fc1b[o];
        float mem  = g_mem2[b*256 + o];
        float rst  = (mem - th > 0.f) ? 1.f : 0.f;
        float memn = fmaf(0.5f, mem, cur) - rst*th;
        g_mem2[b*256 + o] = memn;
        float spk = (memn - th > 0.f) ? 1.f : 0.f;
        sspk2[o] = spk;
        size_t oi = ((size_t)ts*NB + b)*256 + o;
        out[O_SPK2 + oi] = spk;
        out[O_MEM2 + oi] = memn;
    }
    __syncthreads();

    if (tid < 32) {
        float a0 = 0.f, e0 = 0.f, a1 = 0.f, e1 = 0.f;
        #pragma unroll
        for (int j = 0; j < 8; j++) {
            int o = tid + 32*j;
            float s = sspk2[o];
            kadd(a0, e0, fc2w[o] * s);
            kadd(a1, e1, fc2w[256 + o] * s);
        }
        #pragma unroll
        for (int sh = 16; sh; sh >>= 1) {
            float s2 = __shfl_down_sync(0xffffffffu, a0, sh);
            float c2 = __shfl_down_sync(0xffffffffu, e0, sh);
            float ttv, ee;
            twoSum(a0, s2, ttv, ee);
            e0 = (e0 + c2) + ee; a0 = ttv;
            s2 = __shfl_down_sync(0xffffffffu, a1, sh);
            c2 = __shfl_down_sync(0xffffffffu, e1, sh);
            twoSum(a1, s2, ttv, ee);
            e1 = (e1 + c2) + ee; a1 = ttv;
        }
        if (tid == 0) {
            float th = thr[3];
            float cc[2] = {(a0 + e0) + fc2b[0], (a1 + e1) + fc2b[1]};
            #pragma unroll
            for (int r = 0; r < 2; r++) {
                float mem  = g_mem3[b*2 + r];
                float rst  = (mem - th > 0.f) ? 1.f : 0.f;
                float memn = fmaf(0.5f, mem, cc[r]) - rst*th;
                g_mem3[b*2 + r] = memn;
                float spk = (memn - th > 0.f) ? 1.f : 0.f;
                size_t oi = ((size_t)ts*NB + b)*2 + r;
                out[O_SPK3 + oi] = spk;
                out[O_MEM3 + oi] = memn;
            }
        }
    }
}

// ================= stage2 body: conv2 LUT + maxpool + LIF1 + avgpool counts ==
__device__ __forceinline__ void stage2_body(
        char* sm, int g, int b, int t,
        const float* __restrict__ b2, const float* __restrict__ thr,
        float* __restrict__ out)
{
    float4*   sT    = (float4*)(sm + SM_T);      // 12*256 float4 = 48KB
    unsigned* smask = (unsigned*)(sm + SM_MASK); // 1032 u32
    float4*   sc    = (float4*)(sm + SM_SC);     // 1023 float4
    float*    saux  = (float*)(sm + SM_AUX);

    int tid = threadIdx.x;
    const unsigned* gm = g_mask[t & 1] + b*L1;

    const float4* lutg = (const float4*)g_lut + (size_t)g*12*256;
    for (int i = tid; i < 12*256; i += 256) sT[i] = lutg[i];
    for (int i = tid; i < 1032; i += 256)
        smask[i] = (i >= 1 && i <= L1) ? gm[i-1] : 0u;
    if (tid < 8) saux[tid] = 0.f;
    if (tid >= 8 && tid < 12) saux[tid] = b2[g*4 + (tid-8)];
    if (tid == 12) saux[12] = thr[1];
    __syncthreads();

    // pass A: conv outputs (unconditional lookups; LUT[0] rows are exactly +0)
    {
        int q0 = tid*4;
        unsigned mm[6];
        #pragma unroll
        for (int j = 0; j < 6; j++) mm[j] = smask[q0 + j];
        #pragma unroll
        for (int i = 0; i < 4; i++) {
            int q = q0 + i;
            if (q < L1) {
                float4 acc = make_float4(0.f, 0.f, 0.f, 0.f);
                #pragma unroll
                for (int k = 0; k < 3; k++) {
                    unsigned m = mm[i + k];
                    unsigned v0 = m & 255u, v1 = (m >> 8) & 255u;
                    unsigned v2 = (m >> 16) & 255u, v3 = m >> 24;
                    const float4* tk = sT + k*4*256;
                    float4 l0  = tk[v0];
                    float4 l1  = tk[256 + v1];
                    float4 l2v = tk[512 + v2];
                    float4 l3  = tk[768 + v3];
                    acc.x += (l0.x + l1.x) + (l2v.x + l3.x);
                    acc.y += (l0.y + l1.y) + (l2v.y + l3.y);
                    acc.z += (l0.z + l1.z) + (l2v.z + l3.z);
                    acc.w += (l0.w + l1.w) + (l2v.w + l3.w);
                }
                sc[q] = acc;
            }
        }
    }
    __syncthreads();

    // pass B: maxpool + LIF1 + writes + spike counts
    const float th = saux[12];
    const float bs0 = saux[8], bs1 = saux[9], bs2 = saux[10], bs3 = saux[11];
    float cnt0[4] = {0.f,0.f,0.f,0.f}, cnt1[4] = {0.f,0.f,0.f,0.f};

    for (int l = tid; l < L2; l += 256) {
        float4 c0 = sc[2*l], c1 = sc[2*l + 1], c2 = sc[2*l + 2];
        float cur[4];
        cur[0] = fmaxf(c0.x + bs0, fmaxf(c1.x + bs0, c2.x + bs0));
        cur[1] = fmaxf(c0.y + bs1, fmaxf(c1.y + bs1, c2.y + bs1));
        cur[2] = fmaxf(c0.z + bs2, fmaxf(c1.z + bs2, c2.z + bs2));
        cur[3] = fmaxf(c0.w + bs3, fmaxf(c1.w + bs3, c2.w + bs3));
        #pragma unroll
        for (int o = 0; o < 4; o++) {
            int oc = g*4 + o;
            int sidx = (b*C2 + oc)*L2 + l;
            float mem  = g_mem1[sidx];
            float rst  = (mem - th > 0.f) ? 1.f : 0.f;
            float memn = fmaf(0.5f, mem, cur[o]) - rst*th;
            g_mem1[sidx] = memn;
            float spk = (memn - th > 0.f) ? 1.f : 0.f;
            size_t oi = ((size_t)t*NB + b)*32704 + (size_t)oc*L2 + l;
            out[O_SPK1 + oi] = spk;
            out[O_MEM1 + oi] = memn;
            if (l < 256)  cnt0[o] += spk;
            if (l >= 255) cnt1[o] += spk;
        }
    }

    {
        int lane = tid & 31;
        #pragma unroll
        for (int o = 0; o < 4; o++) {
            float a = cnt0[o], c = cnt1[o];
            #pragma unroll
            for (int sh = 16; sh; sh >>= 1) {
                a += __shfl_down_sync(0xffffffffu, a, sh);
                c += __shfl_down_sync(0xffffffffu, c, sh);
            }
            if (lane == 0) {
                atomicAdd(&saux[o*2 + 0], a);
                atomicAdd(&saux[o*2 + 1], c);
            }
        }
    }
    __syncthreads();
    if (tid < 8)
        g_feat[(size_t)(t&1)*NB*128 + b*128 + g*8 + tid] = saux[tid] * 0.00390625f;
}

// ================= prologue: stage1 for t = 0 =================
__global__ void __launch_bounds__(256) k_pro(
        const float* __restrict__ x, const float* __restrict__ w1,
        const float* __restrict__ b1, const float* __restrict__ thr,
        float* __restrict__ out)
{
    __shared__ float sw[C1*12];
    __shared__ float sb[C1];
    __shared__ float sthr[1];
    stage1_body(sw, sb, sthr, blockIdx.y, blockIdx.x, 0, x, w1, b1, thr, out);
}

// ================= fused: stage2(t) + stage1(t+1) + fc(t-1) =================
// blocks [0,1024): stage2; [1024,1280): stage1(t+1); [1280,1344): fc(t-1)
__global__ void __launch_bounds__(256, 3) k_fused(
        const float* __restrict__ x,
        const float* __restrict__ w1, const float* __restrict__ b1,
        const float* __restrict__ b2,
        const float* __restrict__ fc1w, const float* __restrict__ fc1b,
        const float* __restrict__ fc2w, const float* __restrict__ fc2b,
        const float* __restrict__ thr, float* __restrict__ out, int t)
{
    extern __shared__ char sm[];
    int bid = blockIdx.x;
    if (bid < 1024) {
        stage2_body(sm, bid & 15, bid >> 4, t, b2, thr, out);
    } else if (bid < 1280) {
        if (t + 1 < T_STEPS) {
            int r = bid - 1024;
            float* sw = (float*)sm;
            float* sb = sw + C1*12;
            float* sthr = sb + C1;
            stage1_body(sw, sb, sthr, r >> 2, r & 3, t + 1, x, w1, b1, thr, out);
        }
    } else {
        if (t >= 1)
            fc_block(sm, bid - 1280, t - 1, fc1w, fc1b, fc2w, fc2b, thr, out);
    }
}

// ================= tail: fc for t = 31 =================
__global__ void __launch_bounds__(256) k_tail(
        const float* __restrict__ fc1w, const float* __restrict__ fc1b,
        const float* __restrict__ fc2w, const float* __restrict__ fc2b,
        const float* __restrict__ thr, float* __restrict__ out)
{
    __shared__ char sm[(128 + 256 + 256) * 4];
    fc_block(sm, blockIdx.x, T_STEPS - 1, fc1w, fc1b, fc2w, fc2b, thr, out);
}

extern "C" void kernel_launch(void* const* d_in, const int* in_sizes, int n_in,
                              void* d_out, int out_size)
{
    const float* x   = (const float*)d_in[0];
    const float* c1w = (const float*)d_in[1];
    const float* c1b = (const float*)d_in[2];
    const float* c2w = (const float*)d_in[3];
    const float* c2b = (const float*)d_in[4];
    const float* f1w = (const float*)d_in[5];
    const float* f1b = (const float*)d_in[6];
    const float* f2w = (const float*)d_in[7];
    const float* f2b = (const float*)d_in[8];
    const float* thr = (const float*)d_in[9];
    float* out = (float*)d_out;

    cudaFuncSetAttribute(k_fused, cudaFuncAttributeMaxDynamicSharedMemorySize, SMEM2);

    k_init<<<256, 256>>>();
    k_lut<<<768, 256>>>(c2w);
    k_pro<<<dim3(4, NB), 256>>>(x, c1w, c1b, thr, out);
    for (int t = 0; t < T_STEPS; t++) {
        k_fused<<<1344, 256, SMEM2>>>(x, c1w, c1b, c2b, f1w, f1b, f2w, f2b,
                                      thr, out, t);
    }
    k_tail<<<NB, 256>>>(f1w, f1b, f2w, f2b, thr, out);
}